// round 2
// baseline (speedup 1.0000x reference)
#include <cuda_runtime.h>
#include <cstdint>

#define NB 4096
#define NS 64
#define ND 512
#define NDEPTH 4
#define LN_EPS 1e-5f

#define BM 128
#define BN 128
#define BK 32
#define WLD 132  // 128 + 4 pad floats per W smem row

#define GBLK 256  // persistent grid: 256 blocks x 256 threads (co-resident, <=2/SM)
#define GTHR 256

// Scratch activations (device globals — no cudaMalloc allowed)
static __device__ __align__(128) float g_x[NB * ND];
static __device__ __align__(128) float g_y[NB * ND];
static __device__ __align__(128) float g_v[NB * ND];
static __device__ __align__(128) float g_h[NB * 4 * ND];

// Software grid barrier state (monotonic epoch -> replay-safe)
static __device__ unsigned g_bar = 0;
static __device__ volatile unsigned g_epoch = 0;

__device__ __forceinline__ void grid_bar() {
    __syncthreads();
    if (threadIdx.x == 0) {
        unsigned e = g_epoch;
        __threadfence();
        if (atomicAdd(&g_bar, 1u) == GBLK - 1) {
            g_bar = 0;
            __threadfence();
            g_epoch = e + 1;
        } else {
            while (g_epoch == e) __nanosleep(32);
            __threadfence();
        }
    }
    __syncthreads();
}

__device__ __forceinline__ float warp_sum(float v) {
#pragma unroll
    for (int o = 16; o > 0; o >>= 1) v += __shfl_xor_sync(0xffffffffu, v, o);
    return v;
}

__device__ __forceinline__ uint32_t f2tf(float f) {
    uint32_t r;
    asm("cvt.rna.tf32.f32 %0, %1;" : "=r"(r) : "f"(f));
    return r;
}

__device__ __forceinline__ void cpasync16(void* smem, const void* gmem) {
    uint32_t sa = (uint32_t)__cvta_generic_to_shared(smem);
    asm volatile("cp.async.cg.shared.global [%0], [%1], 16;\n" ::"r"(sa), "l"(gmem));
}

// ---------------------------------------------------------------------------
// Phase: x[row] = bit_emb[a_seq[row,0]] + bit_emb[b_seq[row,0]] + start_state
// warp-per-row, 2048 warps -> 2 rows each
// ---------------------------------------------------------------------------
__device__ void emb0_phase(const int* __restrict__ a_seq, const int* __restrict__ b_seq,
                           const float* __restrict__ emb, const float* __restrict__ start) {
    int gw = blockIdx.x * 8 + (threadIdx.x >> 5);
    int lane = threadIdx.x & 31;
    for (int row = gw; row < NB; row += GBLK * 8) {
        int a = a_seq[row * NS];
        int b = b_seq[row * NS];
        const float4* ea = (const float4*)(emb + (size_t)a * ND);
        const float4* eb = (const float4*)(emb + (size_t)b * ND);
        const float4* ss = (const float4*)start;
        float4* xr = (float4*)(g_x + (size_t)row * ND);
#pragma unroll
        for (int j = 0; j < 4; j++) {
            int c = lane + 32 * j;
            float4 va = ea[c], vb = eb[c], vs = ss[c];
            float4 o;
            o.x = va.x + vb.x + vs.x;
            o.y = va.y + vb.y + vs.y;
            o.z = va.z + vb.z + vs.z;
            o.w = va.w + vb.w + vs.w;
            xr[c] = o;
        }
    }
}

// ---------------------------------------------------------------------------
// Phase: LayerNorm (warp per row, two-pass in registers)
// ---------------------------------------------------------------------------
__device__ void ln_phase(const float* __restrict__ x, float* __restrict__ y,
                         const float* __restrict__ g, const float* __restrict__ b) {
    int gw = blockIdx.x * 8 + (threadIdx.x >> 5);
    int lane = threadIdx.x & 31;
    for (int row = gw; row < NB; row += GBLK * 8) {
        const float4* xr = (const float4*)(x + (size_t)row * ND);
        float4 v[4];
        float s = 0.f;
#pragma unroll
        for (int j = 0; j < 4; j++) {
            v[j] = xr[lane + 32 * j];
            s += v[j].x + v[j].y + v[j].z + v[j].w;
        }
        s = warp_sum(s);
        float mean = s * (1.0f / ND);
        float q = 0.f;
#pragma unroll
        for (int j = 0; j < 4; j++) {
            float cx = v[j].x - mean, cy = v[j].y - mean;
            float cz = v[j].z - mean, cw = v[j].w - mean;
            q += cx * cx + cy * cy + cz * cz + cw * cw;
        }
        q = warp_sum(q);
        float r = rsqrtf(q * (1.0f / ND) + LN_EPS);
        float4* yr = (float4*)(y + (size_t)row * ND);
#pragma unroll
        for (int j = 0; j < 4; j++) {
            int c = lane + 32 * j;
            float4 gg = ((const float4*)g)[c];
            float4 bb = ((const float4*)b)[c];
            float4 o;
            o.x = (v[j].x - mean) * r * gg.x + bb.x;
            o.y = (v[j].y - mean) * r * gg.y + bb.y;
            o.z = (v[j].z - mean) * r * gg.z + bb.z;
            o.w = (v[j].w - mean) * r * gg.w + bb.w;
            yr[c] = o;
        }
    }
}

// ---------------------------------------------------------------------------
// Phase: head logits for step t, then (if t+1 < NS) x += emb[a_{t+1}] + emb[b_{t+1}]
// warp per row
// ---------------------------------------------------------------------------
__device__ void heademb_phase(const float* __restrict__ hw, const float* __restrict__ hb,
                              float* __restrict__ out, const int* __restrict__ a_seq,
                              const int* __restrict__ b_seq, const float* __restrict__ emb,
                              int t) {
    int gw = blockIdx.x * 8 + (threadIdx.x >> 5);
    int lane = threadIdx.x & 31;
    for (int row = gw; row < NB; row += GBLK * 8) {
        float4* xr = (float4*)(g_x + (size_t)row * ND);
        float4 v[4];
        float s0 = 0.f, s1 = 0.f;
#pragma unroll
        for (int j = 0; j < 4; j++) {
            int c = lane + 32 * j;
            v[j] = xr[c];
            const float* e = (const float*)v;
#pragma unroll
            for (int u = 0; u < 4; u++) {
                float xv = (&v[j].x)[u];
                float2 w = ((const float2*)hw)[c * 4 + u];
                s0 += xv * w.x;
                s1 += xv * w.y;
            }
            (void)e;
        }
        s0 = warp_sum(s0);
        s1 = warp_sum(s1);
        if (lane == 0) {
            out[(size_t)row * NS * 2 + t * 2 + 0] = s0 + hb[0];
            out[(size_t)row * NS * 2 + t * 2 + 1] = s1 + hb[1];
        }
        if (t + 1 < NS) {
            int a = a_seq[row * NS + t + 1];
            int b = b_seq[row * NS + t + 1];
            const float4* ea = (const float4*)(emb + (size_t)a * ND);
            const float4* eb = (const float4*)(emb + (size_t)b * ND);
#pragma unroll
            for (int j = 0; j < 4; j++) {
                int c = lane + 32 * j;
                float4 va = ea[c], vb = eb[c];
                float4 o = v[j];
                o.x += va.x + vb.x;
                o.y += va.y + vb.y;
                o.z += va.z + vb.z;
                o.w += va.w + vb.w;
                xr[c] = o;
            }
        }
    }
}

// ---------------------------------------------------------------------------
// Phase: TF32 GEMM over striped 128x128 tiles.
// C = epi(A[M=4096,K] @ W[K,N] + bias), epi = optional ReLU / += C residual.
// ---------------------------------------------------------------------------
__device__ void gemm_phase(const float* __restrict__ A, const float* __restrict__ W,
                           const float* __restrict__ bias, float* __restrict__ C, int K, int N,
                           int ldw, bool relu, bool res, float* sm) {
    float* sA = sm;                // 2 * BM * BK
    float* sW = sm + 2 * BM * BK;  // 2 * BK * WLD

    const int tid = threadIdx.x;
    const int warp = tid >> 5, lane = tid & 31;
    const int wm = warp >> 2, wn = warp & 3;  // 2 x 4 warp grid
    const int gid = lane >> 2, tig = lane & 3;

    const int ntN = N / BN;
    const int ntiles = (NB / BM) * ntN;
    const int KT = K / BK;

    for (int tile = blockIdx.x; tile < ntiles; tile += GBLK) {
        const int bm = tile / ntN, bn = tile % ntN;
        const float* Ag = A + (size_t)bm * BM * K;
        const float* Wg = W + (size_t)bn * BN;

        float acc[4][4][4];
#pragma unroll
        for (int i = 0; i < 4; i++)
#pragma unroll
            for (int j = 0; j < 4; j++)
#pragma unroll
                for (int k = 0; k < 4; k++) acc[i][j][k] = 0.f;

        auto load_tiles = [&](int kt, int buf) {
            float* dA = sA + buf * BM * BK;
            const float* srcA = Ag + kt * BK;
#pragma unroll
            for (int i = 0; i < 4; i++) {
                int c = tid + i * 256;
                int row = c >> 3, cc = c & 7;  // 8 x 16B per A row
                int sc = cc ^ (row & 7);       // XOR swizzle
                cpasync16(dA + row * BK + sc * 4, srcA + (size_t)row * K + cc * 4);
            }
            float* dW = sW + buf * BK * WLD;
            const float* srcW = Wg + (size_t)kt * BK * ldw;
#pragma unroll
            for (int i = 0; i < 4; i++) {
                int c = tid + i * 256;
                int row = c >> 5, cc = c & 31;  // 32 x 16B per W row
                cpasync16(dW + row * WLD + cc * 4, srcW + (size_t)row * ldw + cc * 4);
            }
            asm volatile("cp.async.commit_group;\n");
        };

        load_tiles(0, 0);

        for (int kt = 0; kt < KT; ++kt) {
            if (kt + 1 < KT) {
                load_tiles(kt + 1, (kt + 1) & 1);
                asm volatile("cp.async.wait_group 1;\n");
            } else {
                asm volatile("cp.async.wait_group 0;\n");
            }
            __syncthreads();
            const float* a_ = sA + (kt & 1) * BM * BK;
            const float* w_ = sW + (kt & 1) * BK * WLD;
#pragma unroll
            for (int ks = 0; ks < 4; ++ks) {
                const int k0 = ks * 8 + tig;
                const int k1 = k0 + 4;
                uint32_t af[4][4];
#pragma unroll
                for (int mi = 0; mi < 4; ++mi) {
                    int r0 = wm * 64 + mi * 16 + gid;
                    int r1 = r0 + 8;
                    af[mi][0] = f2tf(a_[r0 * BK + (((k0 >> 2) ^ (r0 & 7)) << 2) + (k0 & 3)]);
                    af[mi][1] = f2tf(a_[r1 * BK + (((k0 >> 2) ^ (r1 & 7)) << 2) + (k0 & 3)]);
                    af[mi][2] = f2tf(a_[r0 * BK + (((k1 >> 2) ^ (r0 & 7)) << 2) + (k1 & 3)]);
                    af[mi][3] = f2tf(a_[r1 * BK + (((k1 >> 2) ^ (r1 & 7)) << 2) + (k1 & 3)]);
                }
#pragma unroll
                for (int ni = 0; ni < 4; ++ni) {
                    int n = wn * 32 + ni * 8 + gid;
                    uint32_t b0 = f2tf(w_[k0 * WLD + n]);
                    uint32_t b1 = f2tf(w_[k1 * WLD + n]);
#pragma unroll
                    for (int mi = 0; mi < 4; ++mi) {
                        asm volatile(
                            "mma.sync.aligned.m16n8k8.row.col.f32.tf32.tf32.f32 "
                            "{%0,%1,%2,%3},{%4,%5,%6,%7},{%8,%9},{%0,%1,%2,%3};\n"
                            : "+f"(acc[mi][ni][0]), "+f"(acc[mi][ni][1]),
                              "+f"(acc[mi][ni][2]), "+f"(acc[mi][ni][3])
                            : "r"(af[mi][0]), "r"(af[mi][1]), "r"(af[mi][2]), "r"(af[mi][3]),
                              "r"(b0), "r"(b1));
                    }
                }
            }
            __syncthreads();
        }

        // Epilogue: bias, optional residual, optional ReLU
#pragma unroll
        for (int mi = 0; mi < 4; mi++) {
            int row0 = bm * BM + wm * 64 + mi * 16 + gid;
#pragma unroll
            for (int ni = 0; ni < 4; ni++) {
                int col = bn * BN + wn * 32 + ni * 8 + tig * 2;
                float2 bv = *(const float2*)(bias + col);
                float2 v0, v1;
                v0.x = acc[mi][ni][0] + bv.x;
                v0.y = acc[mi][ni][1] + bv.y;
                v1.x = acc[mi][ni][2] + bv.x;
                v1.y = acc[mi][ni][3] + bv.y;
                float2* p0 = (float2*)(C + (size_t)row0 * N + col);
                float2* p1 = (float2*)(C + (size_t)(row0 + 8) * N + col);
                if (res) {
                    float2 r0v = *p0, r1v = *p1;
                    v0.x += r0v.x;
                    v0.y += r0v.y;
                    v1.x += r1v.x;
                    v1.y += r1v.y;
                }
                if (relu) {
                    v0.x = fmaxf(v0.x, 0.f);
                    v0.y = fmaxf(v0.y, 0.f);
                    v1.x = fmaxf(v1.x, 0.f);
                    v1.y = fmaxf(v1.y, 0.f);
                }
                *p0 = v0;
                *p1 = v1;
            }
        }
    }
}

// ---------------------------------------------------------------------------
// Persistent kernel: whole 64-step recurrence in one launch (1 graph node).
// ---------------------------------------------------------------------------
__global__ __launch_bounds__(GTHR, 2) void persistent_kernel(
    const int* __restrict__ a_seq, const int* __restrict__ b_seq,
    const float* __restrict__ bit_emb, const float* __restrict__ start_state,
    const float* __restrict__ ln1_g, const float* __restrict__ ln1_b,
    const float* __restrict__ qkv_w, const float* __restrict__ qkv_b,
    const float* __restrict__ out_w, const float* __restrict__ out_b,
    const float* __restrict__ ln2_g, const float* __restrict__ ln2_b,
    const float* __restrict__ ff1_w, const float* __restrict__ ff1_b,
    const float* __restrict__ ff2_w, const float* __restrict__ ff2_b,
    const float* __restrict__ head_w, const float* __restrict__ head_b, float* __restrict__ out) {
    extern __shared__ float sm[];

    emb0_phase(a_seq, b_seq, bit_emb, start_state);
    grid_bar();

    for (int t = 0; t < NS; ++t) {
        for (int l = 0; l < NDEPTH; ++l) {
            // y = LN1(x)
            ln_phase(g_x, g_y, ln1_g + l * ND, ln1_b + l * ND);
            grid_bar();
            // v = y @ qkv_w[l][:, 2D:3D] + qkv_b[l][2D:3D]
            gemm_phase(g_y, qkv_w + (size_t)l * ND * 3 * ND + 2 * ND,
                       qkv_b + (size_t)l * 3 * ND + 2 * ND, g_v, ND, ND, 3 * ND, false, false, sm);
            grid_bar();
            // x += v @ out_w[l] + out_b[l]
            gemm_phase(g_v, out_w + (size_t)l * ND * ND, out_b + (size_t)l * ND, g_x, ND, ND, ND,
                       false, true, sm);
            grid_bar();
            // y = LN2(x)
            ln_phase(g_x, g_y, ln2_g + l * ND, ln2_b + l * ND);
            grid_bar();
            // h = relu(y @ ff1_w[l] + ff1_b[l])
            gemm_phase(g_y, ff1_w + (size_t)l * ND * 4 * ND, ff1_b + (size_t)l * 4 * ND, g_h, ND,
                       4 * ND, 4 * ND, true, false, sm);
            grid_bar();
            // x += h @ ff2_w[l] + ff2_b[l]
            gemm_phase(g_h, ff2_w + (size_t)l * 4 * ND * ND, ff2_b + (size_t)l * ND, g_x, 4 * ND,
                       ND, ND, false, true, sm);
            grid_bar();
        }
        // logits[:, t, :] = x @ head_w + head_b ; then x += emb(t+1)
        heademb_phase(head_w, head_b, out, a_seq, b_seq, bit_emb, t);
        grid_bar();
    }
}

// ---------------------------------------------------------------------------
extern "C" void kernel_launch(void* const* d_in, const int* in_sizes, int n_in,
                              void* d_out, int out_size) {
    const int* a_seq = (const int*)d_in[0];
    const int* b_seq = (const int*)d_in[1];
    const float* bit_emb = (const float*)d_in[2];
    const float* start_state = (const float*)d_in[3];
    const float* ln1_g = (const float*)d_in[4];
    const float* ln1_b = (const float*)d_in[5];
    const float* qkv_w = (const float*)d_in[6];
    const float* qkv_b = (const float*)d_in[7];
    const float* out_w = (const float*)d_in[8];
    const float* out_b = (const float*)d_in[9];
    const float* ln2_g = (const float*)d_in[10];
    const float* ln2_b = (const float*)d_in[11];
    const float* ff1_w = (const float*)d_in[12];
    const float* ff1_b = (const float*)d_in[13];
    const float* ff2_w = (const float*)d_in[14];
    const float* ff2_b = (const float*)d_in[15];
    const float* head_w = (const float*)d_in[16];
    const float* head_b = (const float*)d_in[17];
    float* out = (float*)d_out;

    const int smem = (2 * BM * BK + 2 * BK * WLD) * (int)sizeof(float);
    static int configured = 0;
    if (!configured) {
        cudaFuncSetAttribute(persistent_kernel, cudaFuncAttributeMaxDynamicSharedMemorySize, smem);
        configured = 1;
    }

    persistent_kernel<<<GBLK, GTHR, smem>>>(a_seq, b_seq, bit_emb, start_state, ln1_g, ln1_b,
                                            qkv_w, qkv_b, out_w, out_b, ln2_g, ln2_b, ff1_w, ff1_b,
                                            ff2_w, ff2_b, head_w, head_b, out);
}

// round 3
// speedup vs baseline: 1.0874x; 1.0874x over previous
#include <cuda_runtime.h>
#include <cstdint>

#define NB 4096
#define NS 64
#define ND 512
#define NDEPTH 4
#define LN_EPS 1e-5f

#define BM 128
#define BN 64
#define BK 32
#define WLD 72  // 64 + 8 pad floats per W smem row (keeps B LDS conflict-free)

#define GBLK 256  // persistent grid: 256 blocks x 256 threads (co-resident, <=2/SM)
#define GTHR 256

// Scratch activations (device globals — no cudaMalloc allowed)
static __device__ __align__(128) float g_x[NB * ND];
static __device__ __align__(128) float g_y[NB * ND];
static __device__ __align__(128) float g_v[NB * ND];
static __device__ __align__(128) float g_h[NB * 4 * ND];

// Software grid barrier state (monotonic epoch -> replay-safe)
static __device__ unsigned g_bar = 0;
static __device__ volatile unsigned g_epoch = 0;

__device__ __forceinline__ void grid_bar() {
    __syncthreads();
    if (threadIdx.x == 0) {
        unsigned e = g_epoch;
        __threadfence();
        if (atomicAdd(&g_bar, 1u) == GBLK - 1) {
            g_bar = 0;
            __threadfence();
            g_epoch = e + 1;
        } else {
            while (g_epoch == e) __nanosleep(32);
            __threadfence();
        }
    }
    __syncthreads();
}

__device__ __forceinline__ float warp_sum(float v) {
#pragma unroll
    for (int o = 16; o > 0; o >>= 1) v += __shfl_xor_sync(0xffffffffu, v, o);
    return v;
}

__device__ __forceinline__ void cpasync16(void* smem, const void* gmem) {
    uint32_t sa = (uint32_t)__cvta_generic_to_shared(smem);
    asm volatile("cp.async.cg.shared.global [%0], [%1], 16;\n" ::"r"(sa), "l"(gmem));
}

// ---------------------------------------------------------------------------
// Phase: x[row] = bit_emb[a_seq[row,0]] + bit_emb[b_seq[row,0]] + start_state
// ---------------------------------------------------------------------------
__device__ void emb0_phase(const int* __restrict__ a_seq, const int* __restrict__ b_seq,
                           const float* __restrict__ emb, const float* __restrict__ start) {
    int gw = blockIdx.x * 8 + (threadIdx.x >> 5);
    int lane = threadIdx.x & 31;
    for (int row = gw; row < NB; row += GBLK * 8) {
        int a = a_seq[row * NS];
        int b = b_seq[row * NS];
        const float4* ea = (const float4*)(emb + (size_t)a * ND);
        const float4* eb = (const float4*)(emb + (size_t)b * ND);
        const float4* ss = (const float4*)start;
        float4* xr = (float4*)(g_x + (size_t)row * ND);
#pragma unroll
        for (int j = 0; j < 4; j++) {
            int c = lane + 32 * j;
            float4 va = ea[c], vb = eb[c], vs = ss[c];
            float4 o;
            o.x = va.x + vb.x + vs.x;
            o.y = va.y + vb.y + vs.y;
            o.z = va.z + vb.z + vs.z;
            o.w = va.w + vb.w + vs.w;
            xr[c] = o;
        }
    }
}

// ---------------------------------------------------------------------------
// Phase: LayerNorm (warp per row)
// ---------------------------------------------------------------------------
__device__ void ln_phase(const float* __restrict__ x, float* __restrict__ y,
                         const float* __restrict__ g, const float* __restrict__ b) {
    int gw = blockIdx.x * 8 + (threadIdx.x >> 5);
    int lane = threadIdx.x & 31;
    for (int row = gw; row < NB; row += GBLK * 8) {
        const float4* xr = (const float4*)(x + (size_t)row * ND);
        float4 v[4];
        float s = 0.f;
#pragma unroll
        for (int j = 0; j < 4; j++) {
            v[j] = xr[lane + 32 * j];
            s += v[j].x + v[j].y + v[j].z + v[j].w;
        }
        s = warp_sum(s);
        float mean = s * (1.0f / ND);
        float q = 0.f;
#pragma unroll
        for (int j = 0; j < 4; j++) {
            float cx = v[j].x - mean, cy = v[j].y - mean;
            float cz = v[j].z - mean, cw = v[j].w - mean;
            q += cx * cx + cy * cy + cz * cz + cw * cw;
        }
        q = warp_sum(q);
        float r = rsqrtf(q * (1.0f / ND) + LN_EPS);
        float4* yr = (float4*)(y + (size_t)row * ND);
#pragma unroll
        for (int j = 0; j < 4; j++) {
            int c = lane + 32 * j;
            float4 gg = ((const float4*)g)[c];
            float4 bb = ((const float4*)b)[c];
            float4 o;
            o.x = (v[j].x - mean) * r * gg.x + bb.x;
            o.y = (v[j].y - mean) * r * gg.y + bb.y;
            o.z = (v[j].z - mean) * r * gg.z + bb.z;
            o.w = (v[j].w - mean) * r * gg.w + bb.w;
            yr[c] = o;
        }
    }
}

// ---------------------------------------------------------------------------
// Phase: head logits for step t, then (if t+1 < NS) x += emb[a_{t+1}] + emb[b_{t+1}]
// ---------------------------------------------------------------------------
__device__ void heademb_phase(const float* __restrict__ hw, const float* __restrict__ hb,
                              float* __restrict__ out, const int* __restrict__ a_seq,
                              const int* __restrict__ b_seq, const float* __restrict__ emb,
                              int t) {
    int gw = blockIdx.x * 8 + (threadIdx.x >> 5);
    int lane = threadIdx.x & 31;
    for (int row = gw; row < NB; row += GBLK * 8) {
        float4* xr = (float4*)(g_x + (size_t)row * ND);
        float4 v[4];
        float s0 = 0.f, s1 = 0.f;
#pragma unroll
        for (int j = 0; j < 4; j++) {
            int c = lane + 32 * j;
            v[j] = xr[c];
#pragma unroll
            for (int u = 0; u < 4; u++) {
                float xv = (&v[j].x)[u];
                float2 w = ((const float2*)hw)[c * 4 + u];
                s0 += xv * w.x;
                s1 += xv * w.y;
            }
        }
        s0 = warp_sum(s0);
        s1 = warp_sum(s1);
        if (lane == 0) {
            out[(size_t)row * NS * 2 + t * 2 + 0] = s0 + hb[0];
            out[(size_t)row * NS * 2 + t * 2 + 1] = s1 + hb[1];
        }
        if (t + 1 < NS) {
            int a = a_seq[row * NS + t + 1];
            int b = b_seq[row * NS + t + 1];
            const float4* ea = (const float4*)(emb + (size_t)a * ND);
            const float4* eb = (const float4*)(emb + (size_t)b * ND);
#pragma unroll
            for (int j = 0; j < 4; j++) {
                int c = lane + 32 * j;
                float4 va = ea[c], vb = eb[c];
                float4 o = v[j];
                o.x += va.x + vb.x;
                o.y += va.y + vb.y;
                o.z += va.z + vb.z;
                o.w += va.w + vb.w;
                xr[c] = o;
            }
        }
    }
}

// ---------------------------------------------------------------------------
// Phase: TF32 GEMM over striped 128x64 tiles (raw-f32 fed to HMMA.TF32).
// C = epi(A[M=4096,K] @ W[K,N] + bias), epi = optional ReLU / += C residual.
// 8 warps in 4x2; warp tile 32x32; mma m16n8k8; cp.async double buffer.
// ---------------------------------------------------------------------------
__device__ void gemm_phase(const float* __restrict__ A, const float* __restrict__ W,
                           const float* __restrict__ bias, float* __restrict__ C, int K, int N,
                           int ldw, bool relu, bool res, float* sm) {
    float* sA = sm;                // 2 * BM * BK = 8192 floats
    float* sW = sm + 2 * BM * BK;  // 2 * BK * WLD = 4608 floats

    const int tid = threadIdx.x;
    const int warp = tid >> 5, lane = tid & 31;
    const int wm = warp >> 1, wn = warp & 1;  // 4 x 2 warp grid
    const int gid = lane >> 2, tig = lane & 3;

    // Per-thread invariant offsets
    const int ar0 = wm * 32 + gid;           // rows ar0, +8, +16, +24
    const int nb = wn * 32 + gid;            // B col base (ni adds 8)
    const int bbase = tig * WLD + nb;        // B smem base (k = tig)

    const int ntN = N / BN;
    const int ntiles = (NB / BM) * ntN;
    const int KT = K / BK;

    for (int tile = blockIdx.x; tile < ntiles; tile += GBLK) {
        const int bm = tile / ntN, bn = tile % ntN;
        const float* Ag = A + (size_t)bm * BM * K;
        const float* Wg = W + (size_t)bn * BN;

        float acc[2][4][4];
#pragma unroll
        for (int i = 0; i < 2; i++)
#pragma unroll
            for (int j = 0; j < 4; j++)
#pragma unroll
                for (int k = 0; k < 4; k++) acc[i][j][k] = 0.f;

        auto load_tiles = [&](int kt, int buf) {
            float* dA = sA + buf * BM * BK;
            const float* srcA = Ag + kt * BK;
#pragma unroll
            for (int i = 0; i < 4; i++) {
                int c = tid + i * 256;
                int row = c >> 3, cc = c & 7;  // 8 x 16B per A row
                int sc = cc ^ (row & 7);       // XOR swizzle
                cpasync16(dA + row * BK + sc * 4, srcA + (size_t)row * K + cc * 4);
            }
            float* dW = sW + buf * BK * WLD;
            const float* srcW = Wg + (size_t)kt * BK * ldw;
#pragma unroll
            for (int i = 0; i < 2; i++) {
                int c = tid + i * 256;
                int row = c >> 4, cc = c & 15;  // 16 x 16B per W row
                cpasync16(dW + row * WLD + cc * 4, srcW + (size_t)row * ldw + cc * 4);
            }
            asm volatile("cp.async.commit_group;\n");
        };

        load_tiles(0, 0);

        for (int kt = 0; kt < KT; ++kt) {
            if (kt + 1 < KT) {
                load_tiles(kt + 1, (kt + 1) & 1);
                asm volatile("cp.async.wait_group 1;\n");
            } else {
                asm volatile("cp.async.wait_group 0;\n");
            }
            __syncthreads();
            const float* a_ = sA + (kt & 1) * BM * BK;
            const float* w_ = sW + (kt & 1) * BK * WLD;
#pragma unroll
            for (int ks = 0; ks < 4; ++ks) {
                // A fragment addresses: r*32 + ((2ks+half)^gid)*4 + tig
                const int x0 = ((2 * ks) ^ gid) * 4 + tig;      // k-half 0
                const int x1 = ((2 * ks + 1) ^ gid) * 4 + tig;  // k-half 1
                uint32_t af[2][4];
#pragma unroll
                for (int mi = 0; mi < 2; ++mi) {
                    const int r0 = (ar0 + mi * 16) * BK;
                    const int r1 = r0 + 8 * BK;
                    af[mi][0] = __float_as_uint(a_[r0 + x0]);
                    af[mi][1] = __float_as_uint(a_[r1 + x0]);
                    af[mi][2] = __float_as_uint(a_[r0 + x1]);
                    af[mi][3] = __float_as_uint(a_[r1 + x1]);
                }
                const int bk = bbase + ks * 8 * WLD;
#pragma unroll
                for (int ni = 0; ni < 4; ++ni) {
                    uint32_t b0 = __float_as_uint(w_[bk + ni * 8]);
                    uint32_t b1 = __float_as_uint(w_[bk + 4 * WLD + ni * 8]);
#pragma unroll
                    for (int mi = 0; mi < 2; ++mi) {
                        asm volatile(
                            "mma.sync.aligned.m16n8k8.row.col.f32.tf32.tf32.f32 "
                            "{%0,%1,%2,%3},{%4,%5,%6,%7},{%8,%9},{%0,%1,%2,%3};\n"
                            : "+f"(acc[mi][ni][0]), "+f"(acc[mi][ni][1]),
                              "+f"(acc[mi][ni][2]), "+f"(acc[mi][ni][3])
                            : "r"(af[mi][0]), "r"(af[mi][1]), "r"(af[mi][2]), "r"(af[mi][3]),
                              "r"(b0), "r"(b1));
                    }
                }
            }
            __syncthreads();
        }

        // Epilogue: bias, optional residual, optional ReLU
#pragma unroll
        for (int mi = 0; mi < 2; mi++) {
            int row0 = bm * BM + wm * 32 + mi * 16 + gid;
#pragma unroll
            for (int ni = 0; ni < 4; ni++) {
                int col = bn * BN + wn * 32 + ni * 8 + tig * 2;
                float2 bv = *(const float2*)(bias + col);
                float2 v0, v1;
                v0.x = acc[mi][ni][0] + bv.x;
                v0.y = acc[mi][ni][1] + bv.y;
                v1.x = acc[mi][ni][2] + bv.x;
                v1.y = acc[mi][ni][3] + bv.y;
                float2* p0 = (float2*)(C + (size_t)row0 * N + col);
                float2* p1 = (float2*)(C + (size_t)(row0 + 8) * N + col);
                if (res) {
                    float2 r0v = *p0, r1v = *p1;
                    v0.x += r0v.x;
                    v0.y += r0v.y;
                    v1.x += r1v.x;
                    v1.y += r1v.y;
                }
                if (relu) {
                    v0.x = fmaxf(v0.x, 0.f);
                    v0.y = fmaxf(v0.y, 0.f);
                    v1.x = fmaxf(v1.x, 0.f);
                    v1.y = fmaxf(v1.y, 0.f);
                }
                *p0 = v0;
                *p1 = v1;
            }
        }
    }
}

// ---------------------------------------------------------------------------
// Persistent kernel: whole 64-step recurrence in one launch (1 graph node).
// ---------------------------------------------------------------------------
__global__ __launch_bounds__(GTHR, 2) void persistent_kernel(
    const int* __restrict__ a_seq, const int* __restrict__ b_seq,
    const float* __restrict__ bit_emb, const float* __restrict__ start_state,
    const float* __restrict__ ln1_g, const float* __restrict__ ln1_b,
    const float* __restrict__ qkv_w, const float* __restrict__ qkv_b,
    const float* __restrict__ out_w, const float* __restrict__ out_b,
    const float* __restrict__ ln2_g, const float* __restrict__ ln2_b,
    const float* __restrict__ ff1_w, const float* __restrict__ ff1_b,
    const float* __restrict__ ff2_w, const float* __restrict__ ff2_b,
    const float* __restrict__ head_w, const float* __restrict__ head_b, float* __restrict__ out) {
    extern __shared__ float sm[];

    emb0_phase(a_seq, b_seq, bit_emb, start_state);
    grid_bar();

    for (int t = 0; t < NS; ++t) {
        for (int l = 0; l < NDEPTH; ++l) {
            // y = LN1(x)
            ln_phase(g_x, g_y, ln1_g + l * ND, ln1_b + l * ND);
            grid_bar();
            // v = y @ qkv_w[l][:, 2D:3D] + qkv_b[l][2D:3D]
            gemm_phase(g_y, qkv_w + (size_t)l * ND * 3 * ND + 2 * ND,
                       qkv_b + (size_t)l * 3 * ND + 2 * ND, g_v, ND, ND, 3 * ND, false, false, sm);
            grid_bar();
            // x += v @ out_w[l] + out_b[l]
            gemm_phase(g_v, out_w + (size_t)l * ND * ND, out_b + (size_t)l * ND, g_x, ND, ND, ND,
                       false, true, sm);
            grid_bar();
            // y = LN2(x)
            ln_phase(g_x, g_y, ln2_g + l * ND, ln2_b + l * ND);
            grid_bar();
            // h = relu(y @ ff1_w[l] + ff1_b[l])
            gemm_phase(g_y, ff1_w + (size_t)l * ND * 4 * ND, ff1_b + (size_t)l * 4 * ND, g_h, ND,
                       4 * ND, 4 * ND, true, false, sm);
            grid_bar();
            // x += h @ ff2_w[l] + ff2_b[l]
            gemm_phase(g_h, ff2_w + (size_t)l * 4 * ND * ND, ff2_b + (size_t)l * ND, g_x, 4 * ND,
                       ND, ND, false, true, sm);
            grid_bar();
        }
        // logits[:, t, :] = x @ head_w + head_b ; then x += emb(t+1)
        heademb_phase(head_w, head_b, out, a_seq, b_seq, bit_emb, t);
        grid_bar();
    }
}

// ---------------------------------------------------------------------------
extern "C" void kernel_launch(void* const* d_in, const int* in_sizes, int n_in,
                              void* d_out, int out_size) {
    const int* a_seq = (const int*)d_in[0];
    const int* b_seq = (const int*)d_in[1];
    const float* bit_emb = (const float*)d_in[2];
    const float* start_state = (const float*)d_in[3];
    const float* ln1_g = (const float*)d_in[4];
    const float* ln1_b = (const float*)d_in[5];
    const float* qkv_w = (const float*)d_in[6];
    const float* qkv_b = (const float*)d_in[7];
    const float* out_w = (const float*)d_in[8];
    const float* out_b = (const float*)d_in[9];
    const float* ln2_g = (const float*)d_in[10];
    const float* ln2_b = (const float*)d_in[11];
    const float* ff1_w = (const float*)d_in[12];
    const float* ff1_b = (const float*)d_in[13];
    const float* ff2_w = (const float*)d_in[14];
    const float* ff2_b = (const float*)d_in[15];
    const float* head_w = (const float*)d_in[16];
    const float* head_b = (const float*)d_in[17];
    float* out = (float*)d_out;

    const int smem = (2 * BM * BK + 2 * BK * WLD) * (int)sizeof(float);
    static int configured = 0;
    if (!configured) {
        cudaFuncSetAttribute(persistent_kernel, cudaFuncAttributeMaxDynamicSharedMemorySize, smem);
        configured = 1;
    }

    persistent_kernel<<<GBLK, GTHR, smem>>>(a_seq, b_seq, bit_emb, start_state, ln1_g, ln1_b,
                                            qkv_w, qkv_b, out_w, out_b, ln2_g, ln2_b, ff1_w, ff1_b,
                                            ff2_w, ff2_b, head_w, head_b, out);
}